// round 2
// baseline (speedup 1.0000x reference)
#include <cuda_runtime.h>
#include <math.h>
#include <stdint.h>

#define T_TOK 4096
#define H_DIM 1024
#define I_DIM 2816
#define N_EXP 8
#define MAXP  (T_TOK * 2)

#define BM 64
#define BN 64
#define BK 16
#define PAD 4

// ---- scratch (no allocations allowed; __device__ globals) ----
__device__ int   g_counts[N_EXP];
__device__ int   g_tokens[N_EXP][T_TOK];
__device__ float g_scales[N_EXP][T_TOK];
__device__ int   g_slot  [N_EXP][T_TOK];
__device__ float g_h[(size_t)MAXP * I_DIM];      // 92.3 MB
__device__ float g_pair[(size_t)MAXP * H_DIM];   // 33.6 MB

__global__ void zero_counts_kernel() {
    if (threadIdx.x < N_EXP) g_counts[threadIdx.x] = 0;
}

// Softmax over 8 experts, top-2 (first-index tie rule like jax top_k),
// scatter into per-expert buckets via atomics. Pair slot = 2*t + k.
__global__ void router_kernel(const float* __restrict__ logits) {
    int t = blockIdx.x * blockDim.x + threadIdx.x;
    if (t >= T_TOK) return;
    float l[N_EXP];
    float mx = -1e30f;
#pragma unroll
    for (int e = 0; e < N_EXP; e++) { l[e] = logits[t * N_EXP + e]; mx = fmaxf(mx, l[e]); }
    float s = 0.f;
#pragma unroll
    for (int e = 0; e < N_EXP; e++) { l[e] = expf(l[e] - mx); s += l[e]; }
    float inv = 1.f / s;
    int e0 = 0;
#pragma unroll
    for (int e = 1; e < N_EXP; e++) if (l[e] > l[e0]) e0 = e;
    int e1 = (e0 == 0) ? 1 : 0;
#pragma unroll
    for (int e = 0; e < N_EXP; e++) if (e != e0 && l[e] > l[e1]) e1 = e;

    int p0 = atomicAdd(&g_counts[e0], 1);
    g_tokens[e0][p0] = t; g_scales[e0][p0] = l[e0] * inv; g_slot[e0][p0] = 2 * t;
    int p1 = atomicAdd(&g_counts[e1], 1);
    g_tokens[e1][p1] = t; g_scales[e1][p1] = l[e1] * inv; g_slot[e1][p1] = 2 * t + 1;
}

// GEMM1 + SwiGLU: for expert e, rows = gathered x tokens, cols = I columns.
// Computes BOTH u(=w3 x) and g(=w1 x) tiles so SwiGLU fuses in-register.
__global__ __launch_bounds__(256, 2) void gemm1_swiglu_kernel(
        const float* __restrict__ x, const float* __restrict__ w3w1) {
    int e   = blockIdx.z;
    int cnt = g_counts[e];
    int m0  = blockIdx.y * BM;
    if (m0 >= cnt) return;                 // uniform early exit
    int n0  = blockIdx.x * BN;

    __shared__ float As[BK][BM + PAD];
    __shared__ float Bu[BK][BN + PAD];
    __shared__ float Bg[BK][BN + PAD];

    int tid  = threadIdx.x;
    int tx   = tid & 15, ty = tid >> 4;    // 16x16 thread grid, 4x4 microtile
    int lRow = tid >> 2;                   // 0..63
    int lK   = (tid & 3) << 2;             // 0,4,8,12

    const float* wbase = w3w1 + (size_t)e * (2 * I_DIM) * H_DIM;
    const float* xrow  = nullptr;
    int tokRow = m0 + lRow;
    if (tokRow < cnt) xrow = x + (size_t)g_tokens[e][tokRow] * H_DIM + lK;
    const float* wu = wbase + (size_t)(n0 + lRow) * H_DIM + lK;           // w3 (up)
    const float* wg = wbase + (size_t)(I_DIM + n0 + lRow) * H_DIM + lK;   // w1 (gate)

    float acc_u[4][4] = {};
    float acc_g[4][4] = {};

    for (int k0 = 0; k0 < H_DIM; k0 += BK) {
        float4 av = xrow ? *(const float4*)(xrow + k0) : make_float4(0.f, 0.f, 0.f, 0.f);
        float4 bu = *(const float4*)(wu + k0);
        float4 bg = *(const float4*)(wg + k0);
        __syncthreads();
        As[lK + 0][lRow] = av.x; As[lK + 1][lRow] = av.y; As[lK + 2][lRow] = av.z; As[lK + 3][lRow] = av.w;
        Bu[lK + 0][lRow] = bu.x; Bu[lK + 1][lRow] = bu.y; Bu[lK + 2][lRow] = bu.z; Bu[lK + 3][lRow] = bu.w;
        Bg[lK + 0][lRow] = bg.x; Bg[lK + 1][lRow] = bg.y; Bg[lK + 2][lRow] = bg.z; Bg[lK + 3][lRow] = bg.w;
        __syncthreads();
#pragma unroll
        for (int k = 0; k < BK; k++) {
            float4 a4 = *(const float4*)&As[k][ty << 2];
            float4 u4 = *(const float4*)&Bu[k][tx << 2];
            float4 g4 = *(const float4*)&Bg[k][tx << 2];
            float a[4] = {a4.x, a4.y, a4.z, a4.w};
            float u[4] = {u4.x, u4.y, u4.z, u4.w};
            float g[4] = {g4.x, g4.y, g4.z, g4.w};
#pragma unroll
            for (int i = 0; i < 4; i++)
#pragma unroll
                for (int j = 0; j < 4; j++) {
                    acc_u[i][j] = fmaf(a[i], u[j], acc_u[i][j]);
                    acc_g[i][j] = fmaf(a[i], g[j], acc_g[i][j]);
                }
        }
    }

#pragma unroll
    for (int i = 0; i < 4; i++) {
        int row = m0 + (ty << 2) + i;
        if (row < cnt) {
            int slot = g_slot[e][row];
            float4 hv;
            float* o = &hv.x;
#pragma unroll
            for (int j = 0; j < 4; j++) {
                float g   = acc_g[i][j];
                float sig = 1.f / (1.f + __expf(-g));
                o[j] = acc_u[i][j] * (g * sig);      // silu(gate) * up
            }
            *(float4*)(g_h + (size_t)slot * I_DIM + n0 + (tx << 2)) = hv;
        }
    }
}

// GEMM2: y = h @ w2[e]^T, epilogue applies routing scale, writes pair slot.
__global__ __launch_bounds__(256, 2) void gemm2_kernel(const float* __restrict__ w2) {
    int e   = blockIdx.z;
    int cnt = g_counts[e];
    int m0  = blockIdx.y * BM;
    if (m0 >= cnt) return;
    int n0  = blockIdx.x * BN;

    __shared__ float As[BK][BM + PAD];
    __shared__ float Bs[BK][BN + PAD];

    int tid  = threadIdx.x;
    int tx   = tid & 15, ty = tid >> 4;
    int lRow = tid >> 2;
    int lK   = (tid & 3) << 2;

    const float* hrow = nullptr;
    int tokRow = m0 + lRow;
    if (tokRow < cnt) hrow = g_h + (size_t)g_slot[e][tokRow] * I_DIM + lK;
    const float* wr = w2 + (size_t)e * H_DIM * I_DIM + (size_t)(n0 + lRow) * I_DIM + lK;

    float acc[4][4] = {};

    for (int k0 = 0; k0 < I_DIM; k0 += BK) {
        float4 av = hrow ? *(const float4*)(hrow + k0) : make_float4(0.f, 0.f, 0.f, 0.f);
        float4 bv = *(const float4*)(wr + k0);
        __syncthreads();
        As[lK + 0][lRow] = av.x; As[lK + 1][lRow] = av.y; As[lK + 2][lRow] = av.z; As[lK + 3][lRow] = av.w;
        Bs[lK + 0][lRow] = bv.x; Bs[lK + 1][lRow] = bv.y; Bs[lK + 2][lRow] = bv.z; Bs[lK + 3][lRow] = bv.w;
        __syncthreads();
#pragma unroll
        for (int k = 0; k < BK; k++) {
            float4 a4 = *(const float4*)&As[k][ty << 2];
            float4 b4 = *(const float4*)&Bs[k][tx << 2];
            float a[4] = {a4.x, a4.y, a4.z, a4.w};
            float b[4] = {b4.x, b4.y, b4.z, b4.w};
#pragma unroll
            for (int i = 0; i < 4; i++)
#pragma unroll
                for (int j = 0; j < 4; j++)
                    acc[i][j] = fmaf(a[i], b[j], acc[i][j]);
        }
    }

#pragma unroll
    for (int i = 0; i < 4; i++) {
        int row = m0 + (ty << 2) + i;
        if (row < cnt) {
            int slot = g_slot[e][row];
            float sc = g_scales[e][row];
            float4 yv;
            yv.x = acc[i][0] * sc; yv.y = acc[i][1] * sc;
            yv.z = acc[i][2] * sc; yv.w = acc[i][3] * sc;
            *(float4*)(g_pair + (size_t)slot * H_DIM + n0 + (tx << 2)) = yv;
        }
    }
}

// out[t] = pair[2t] + pair[2t+1]  (deterministic combine, no atomics)
__global__ void combine_kernel(float* __restrict__ out) {
    int idx = blockIdx.x * blockDim.x + threadIdx.x;
    const int HV = H_DIM / 4;
    if (idx >= T_TOK * HV) return;
    int t = idx / HV;
    int c = idx - t * HV;
    const float4* p = (const float4*)g_pair;
    float4 a = p[(size_t)(2 * t) * HV + c];
    float4 b = p[(size_t)(2 * t + 1) * HV + c];
    ((float4*)out)[idx] = make_float4(a.x + b.x, a.y + b.y, a.z + b.z, a.w + b.w);
}

extern "C" void kernel_launch(void* const* d_in, const int* in_sizes, int n_in,
                              void* d_out, int out_size) {
    const float* x      = (const float*)d_in[0];
    const float* logits = (const float*)d_in[1];
    const float* w3w1   = (const float*)d_in[2];
    const float* w2     = (const float*)d_in[3];
    float* out = (float*)d_out;

    zero_counts_kernel<<<1, 32>>>();
    router_kernel<<<(T_TOK + 255) / 256, 256>>>(logits);

    dim3 blk(256);
    dim3 g1(I_DIM / BN, T_TOK / BM, N_EXP);   // 44 x 64 x 8, most tiles early-exit
    gemm1_swiglu_kernel<<<g1, blk>>>(x, w3w1);

    dim3 g2(H_DIM / BN, T_TOK / BM, N_EXP);   // 16 x 64 x 8
    gemm2_kernel<<<g2, blk>>>(w2);

    combine_kernel<<<(T_TOK * (H_DIM / 4) + 255) / 256, 256>>>(out);
}

// round 6
// speedup vs baseline: 2.3997x; 2.3997x over previous
#include <cuda_runtime.h>
#include <cuda_bf16.h>
#include <math.h>
#include <stdint.h>

#define T_TOK 4096
#define H_DIM 1024
#define I_DIM 2816
#define N_EXP 8
#define MAXP  (T_TOK * 2)
#define NG1   (2 * I_DIM)      // 5632

// ---- tile config ----
#define BM 128
#define BN 128
#define BKC 64                 // bf16 K elems per smem chunk (128 bytes/row)
#define TILE_BYTES (128 * 128) // 128 rows x 128B
#define OFF_AHI 0
#define OFF_ALO (1 * TILE_BYTES)
#define OFF_BHI (2 * TILE_BYTES)
#define OFF_BLO (3 * TILE_BYTES)
#define STAGE_BYTES (4 * TILE_BYTES)       // 64 KB
#define SMEM_DYN (2 * STAGE_BYTES)         // 128 KB

// ---------------- scratch ----------------
__device__ int   g_counts[N_EXP];
__device__ int   g_tokens[N_EXP][T_TOK];
__device__ float g_scales[N_EXP][T_TOK];
__device__ int   g_slot  [N_EXP][T_TOK];

__device__ __align__(16) __nv_bfloat16 g_xhi[(size_t)T_TOK * H_DIM];
__device__ __align__(16) __nv_bfloat16 g_xlo[(size_t)T_TOK * H_DIM];
__device__ __align__(16) __nv_bfloat16 g_w31hi[(size_t)N_EXP * NG1 * H_DIM];
__device__ __align__(16) __nv_bfloat16 g_w31lo[(size_t)N_EXP * NG1 * H_DIM];
__device__ __align__(16) __nv_bfloat16 g_w2hi[(size_t)N_EXP * H_DIM * I_DIM];
__device__ __align__(16) __nv_bfloat16 g_w2lo[(size_t)N_EXP * H_DIM * I_DIM];
__device__ __align__(16) float g_ug[(size_t)MAXP * NG1];
__device__ __align__(16) __nv_bfloat16 g_hhi[(size_t)MAXP * I_DIM];
__device__ __align__(16) __nv_bfloat16 g_hlo[(size_t)MAXP * I_DIM];
__device__ __align__(16) float g_pair[(size_t)MAXP * H_DIM];

// ---------------- helpers ----------------
__device__ __forceinline__ uint32_t smem_u32(const void* p) {
    uint32_t a;
    asm("{ .reg .u64 t; cvta.to.shared.u64 t, %1; cvt.u32.u64 %0, t; }" : "=r"(a) : "l"(p));
    return a;
}
__device__ __forceinline__ void cp16(uint32_t dst, const void* src, uint32_t sz) {
    asm volatile("cp.async.cg.shared.global [%0], [%1], 16, %2;"
                 :: "r"(dst), "l"(src), "r"(sz) : "memory");
}
#define CP_COMMIT() asm volatile("cp.async.commit_group;" ::: "memory")
#define CP_WAIT0()  asm volatile("cp.async.wait_group 0;" ::: "memory")
#define LDSM_X4(r, addr) \
    asm volatile("ldmatrix.sync.aligned.m8n8.x4.shared.b16 {%0,%1,%2,%3}, [%4];" \
        : "=r"((r)[0]), "=r"((r)[1]), "=r"((r)[2]), "=r"((r)[3]) : "r"(addr))
__device__ __forceinline__ void mma16816(float* c, const uint32_t* a, uint32_t b0, uint32_t b1) {
    asm volatile("mma.sync.aligned.m16n8k16.row.col.f32.bf16.bf16.f32 "
        "{%0,%1,%2,%3}, {%4,%5,%6,%7}, {%8,%9}, {%0,%1,%2,%3};"
        : "+f"(c[0]), "+f"(c[1]), "+f"(c[2]), "+f"(c[3])
        : "r"(a[0]), "r"(a[1]), "r"(a[2]), "r"(a[3]), "r"(b0), "r"(b1));
}

// ---------------- small kernels ----------------
__global__ void zero_counts_kernel() {
    if (threadIdx.x < N_EXP) g_counts[threadIdx.x] = 0;
}

__global__ void router_kernel(const float* __restrict__ logits) {
    int t = blockIdx.x * blockDim.x + threadIdx.x;
    if (t >= T_TOK) return;
    float l[N_EXP];
    float mx = -1e30f;
#pragma unroll
    for (int e = 0; e < N_EXP; e++) { l[e] = logits[t * N_EXP + e]; mx = fmaxf(mx, l[e]); }
    float s = 0.f;
#pragma unroll
    for (int e = 0; e < N_EXP; e++) { l[e] = expf(l[e] - mx); s += l[e]; }
    float inv = 1.f / s;
    int e0 = 0;
#pragma unroll
    for (int e = 1; e < N_EXP; e++) if (l[e] > l[e0]) e0 = e;
    int e1 = (e0 == 0) ? 1 : 0;
#pragma unroll
    for (int e = 0; e < N_EXP; e++) if (e != e0 && l[e] > l[e1]) e1 = e;
    int p0 = atomicAdd(&g_counts[e0], 1);
    g_tokens[e0][p0] = t; g_scales[e0][p0] = l[e0] * inv; g_slot[e0][p0] = 2 * t;
    int p1 = atomicAdd(&g_counts[e1], 1);
    g_tokens[e1][p1] = t; g_scales[e1][p1] = l[e1] * inv; g_slot[e1][p1] = 2 * t + 1;
}

__global__ void split_kernel(const float* __restrict__ src,
                             __nv_bfloat16* __restrict__ hi,
                             __nv_bfloat16* __restrict__ lo, int n4) {
    int i = blockIdx.x * blockDim.x + threadIdx.x;
    if (i >= n4) return;
    float4 v = ((const float4*)src)[i];
    float vv[4] = {v.x, v.y, v.z, v.w};
    __nv_bfloat16 h[4], L[4];
#pragma unroll
    for (int k = 0; k < 4; k++) {
        h[k] = __float2bfloat16(vv[k]);
        L[k] = __float2bfloat16(vv[k] - __bfloat162float(h[k]));
    }
    __nv_bfloat162* h2 = (__nv_bfloat162*)hi;
    __nv_bfloat162* l2 = (__nv_bfloat162*)lo;
    __nv_bfloat162 a; a.x = h[0]; a.y = h[1]; h2[2 * i] = a;
    __nv_bfloat162 b; b.x = h[2]; b.y = h[3]; h2[2 * i + 1] = b;
    __nv_bfloat162 c; c.x = L[0]; c.y = L[1]; l2[2 * i] = c;
    __nv_bfloat162 d; d.x = L[2]; d.y = L[3]; l2[2 * i + 1] = d;
}

__global__ void act_kernel() {
    int slot = blockIdx.y;
    int c4 = blockIdx.x * blockDim.x + threadIdx.x;
    if (c4 >= I_DIM / 4) return;
    const float* base = g_ug + (size_t)slot * NG1;
    float4 u = *(const float4*)(base + 4 * c4);
    float4 g = *(const float4*)(base + I_DIM + 4 * c4);
    float uu[4] = {u.x, u.y, u.z, u.w};
    float gg[4] = {g.x, g.y, g.z, g.w};
    __nv_bfloat16 h[4], L[4];
#pragma unroll
    for (int k = 0; k < 4; k++) {
        float sig = 1.f / (1.f + __expf(-gg[k]));
        float hv = uu[k] * (gg[k] * sig);
        h[k] = __float2bfloat16(hv);
        L[k] = __float2bfloat16(hv - __bfloat162float(h[k]));
    }
    size_t o2 = ((size_t)slot * I_DIM) / 2 + 2 * c4;
    __nv_bfloat162* h2 = (__nv_bfloat162*)g_hhi;
    __nv_bfloat162* l2 = (__nv_bfloat162*)g_hlo;
    __nv_bfloat162 a; a.x = h[0]; a.y = h[1]; h2[o2] = a;
    __nv_bfloat162 b; b.x = h[2]; b.y = h[3]; h2[o2 + 1] = b;
    __nv_bfloat162 c; c.x = L[0]; c.y = L[1]; l2[o2] = c;
    __nv_bfloat162 d; d.x = L[2]; d.y = L[3]; l2[o2 + 1] = d;
}

// ---------------- grouped bf16x3 mma.sync GEMM ----------------
// MODE 0: GEMM1  A=x (gather token), B=w3w1, C=g_ug,  K=1024, no scale
// MODE 1: GEMM2  A=h (gather slot),  B=w2,   C=g_pair, K=2816, scale
template <int MODE>
__global__ __launch_bounds__(256, 1) void moe_gemm_kernel() {
    constexpr int K      = (MODE == 0) ? H_DIM : I_DIM;
    constexpr int LDC    = (MODE == 0) ? NG1 : H_DIM;
    constexpr int CHUNKS = K / BKC;

    int e   = blockIdx.z;
    int cnt = g_counts[e];
    int m0  = blockIdx.y * BM;
    if (m0 >= cnt) return;
    int n0  = blockIdx.x * BN;

    const __nv_bfloat16* Ahi = (MODE == 0) ? g_xhi : g_hhi;
    const __nv_bfloat16* Alo = (MODE == 0) ? g_xlo : g_hlo;
    const __nv_bfloat16* Bhi = (MODE == 0) ? g_w31hi + (size_t)e * NG1 * H_DIM
                                           : g_w2hi  + (size_t)e * H_DIM * I_DIM;
    const __nv_bfloat16* Blo = (MODE == 0) ? g_w31lo + (size_t)e * NG1 * H_DIM
                                           : g_w2lo  + (size_t)e * H_DIM * I_DIM;
    float* C = (MODE == 0) ? g_ug : g_pair;
    const int* idxA = (MODE == 0) ? &g_tokens[e][0] : &g_slot[e][0];

    extern __shared__ char smem[];
    uint32_t sbase = smem_u32(smem);
    int tid  = threadIdx.x;
    int lane = tid & 31;
    int wid  = tid >> 5;
    int wm   = (wid & 1) * 64;      // warp M offset (2 warps along M)
    int wn   = (wid >> 1) * 32;     // warp N offset (4 warps along N)

    // ---- loader mapping: thread -> (rows row0+32r, 16B-unit col16) ----
    int col16 = tid & 7;
    int row0  = tid >> 3;
    uint32_t sw[4];
    const __nv_bfloat16 *aH[4], *aL[4], *bH[4], *bL[4];
    uint32_t asz[4];
#pragma unroll
    for (int r = 0; r < 4; r++) {
        int rt = row0 + 32 * r;
        uint32_t off = rt * 128 + col16 * 16;
        sw[r] = off ^ ((off >> 3) & 0x70);
        int mrow = m0 + rt;
        if (mrow < cnt) {
            size_t rg = (size_t)idxA[mrow];
            aH[r] = Ahi + rg * K + col16 * 8;
            aL[r] = Alo + rg * K + col16 * 8;
            asz[r] = 16;
        } else {
            aH[r] = Ahi; aL[r] = Alo; asz[r] = 0;   // zero-fill
        }
        size_t brow = (size_t)(n0 + rt);
        bH[r] = Bhi + brow * K + col16 * 8;
        bL[r] = Blo + brow * K + col16 * 8;
    }

    auto prefetch = [&](int c) {
        uint32_t st = sbase + (uint32_t)(c & 1) * STAGE_BYTES;
        int k0 = c * BKC;
#pragma unroll
        for (int r = 0; r < 4; r++) {
            cp16(st + OFF_AHI + sw[r], aH[r] + k0, asz[r]);
            cp16(st + OFF_ALO + sw[r], aL[r] + k0, asz[r]);
            cp16(st + OFF_BHI + sw[r], bH[r] + k0, 16);
            cp16(st + OFF_BLO + sw[r], bL[r] + k0, 16);
        }
        CP_COMMIT();
    };

    // ---- ldmatrix address precompute ----
    int kh = lane >> 4;                       // which 16B half (k0-7 / k8-15)
    uint32_t rowOffA[4], rxA[4];
#pragma unroll
    for (int mi = 0; mi < 4; mi++) {
        int ra = wm + mi * 16 + (lane & 15);
        rowOffA[mi] = (uint32_t)ra * 128;
        rxA[mi] = ra & 7;
    }
    uint32_t rowOffB[2], rxB[2];
#pragma unroll
    for (int g = 0; g < 2; g++) {
        int rb = wn + g * 16 + (lane & 15);
        rowOffB[g] = (uint32_t)rb * 128;
        rxB[g] = rb & 7;
    }

    float acc[4][4][4] = {};   // [mi][n8 idx][4]

    prefetch(0);

    for (int c = 0; c < CHUNKS; c++) {
        CP_WAIT0();
        __syncthreads();
        if (c + 1 < CHUNKS) prefetch(c + 1);
        uint32_t st = sbase + (uint32_t)(c & 1) * STAGE_BYTES;

#pragma unroll
        for (int ks = 0; ks < 4; ks++) {
            uint32_t ub = (uint32_t)(ks * 2 + kh);
            uint32_t ah[4][4], al[4][4], bh[2][4], bl[2][4];
#pragma unroll
            for (int mi = 0; mi < 4; mi++) {
                uint32_t ad = st + OFF_AHI + rowOffA[mi] + ((ub ^ rxA[mi]) << 4);
                LDSM_X4(ah[mi], ad);
                ad = st + OFF_ALO + rowOffA[mi] + ((ub ^ rxA[mi]) << 4);
                LDSM_X4(al[mi], ad);
            }
#pragma unroll
            for (int g = 0; g < 2; g++) {
                uint32_t bd = st + OFF_BHI + rowOffB[g] + ((ub ^ rxB[g]) << 4);
                LDSM_X4(bh[g], bd);
                bd = st + OFF_BLO + rowOffB[g] + ((ub ^ rxB[g]) << 4);
                LDSM_X4(bl[g], bd);
            }
#pragma unroll
            for (int mi = 0; mi < 4; mi++)
#pragma unroll
                for (int g = 0; g < 2; g++)
#pragma unroll
                    for (int s = 0; s < 2; s++) {
                        float* a4 = acc[mi][g * 2 + s];
                        mma16816(a4, ah[mi], bh[g][0 + s], bh[g][2 + s]);
                        mma16816(a4, ah[mi], bl[g][0 + s], bl[g][2 + s]);
                        mma16816(a4, al[mi], bh[g][0 + s], bh[g][2 + s]);
                    }
        }
        __syncthreads();
    }

    // ---- epilogue ----
#pragma unroll
    for (int mi = 0; mi < 4; mi++) {
        int r0 = m0 + wm + mi * 16 + (lane >> 2);
        int r1 = r0 + 8;
        int  s0 = 0, s1 = 0;
        float sc0 = 1.f, sc1 = 1.f;
        bool v0 = r0 < cnt, v1 = r1 < cnt;
        if (v0) { s0 = g_slot[e][r0]; if (MODE == 1) sc0 = g_scales[e][r0]; }
        if (v1) { s1 = g_slot[e][r1]; if (MODE == 1) sc1 = g_scales[e][r1]; }
        float* p0 = C + (size_t)s0 * LDC;
        float* p1 = C + (size_t)s1 * LDC;
#pragma unroll
        for (int j = 0; j < 4; j++) {
            int cc = n0 + wn + j * 8 + (lane & 3) * 2;
            if (v0) {
                float2 w = make_float2(acc[mi][j][0] * sc0, acc[mi][j][1] * sc0);
                *(float2*)(p0 + cc) = w;
            }
            if (v1) {
                float2 w = make_float2(acc[mi][j][2] * sc1, acc[mi][j][3] * sc1);
                *(float2*)(p1 + cc) = w;
            }
        }
    }
}

// out[t] = pair[2t] + pair[2t+1]
__global__ void combine_kernel(float* __restrict__ out) {
    int idx = blockIdx.x * blockDim.x + threadIdx.x;
    const int HV = H_DIM / 4;
    if (idx >= T_TOK * HV) return;
    int t = idx / HV;
    int c = idx - t * HV;
    const float4* p = (const float4*)g_pair;
    float4 a = p[(size_t)(2 * t) * HV + c];
    float4 b = p[(size_t)(2 * t + 1) * HV + c];
    ((float4*)out)[idx] = make_float4(a.x + b.x, a.y + b.y, a.z + b.z, a.w + b.w);
}

extern "C" void kernel_launch(void* const* d_in, const int* in_sizes, int n_in,
                              void* d_out, int out_size) {
    const float* x      = (const float*)d_in[0];
    const float* logits = (const float*)d_in[1];
    const float* w3w1   = (const float*)d_in[2];
    const float* w2     = (const float*)d_in[3];
    float* out = (float*)d_out;

    cudaFuncSetAttribute(moe_gemm_kernel<0>, cudaFuncAttributeMaxDynamicSharedMemorySize, SMEM_DYN);
    cudaFuncSetAttribute(moe_gemm_kernel<1>, cudaFuncAttributeMaxDynamicSharedMemorySize, SMEM_DYN);

    zero_counts_kernel<<<1, 32>>>();
    router_kernel<<<(T_TOK + 255) / 256, 256>>>(logits);

    {
        __nv_bfloat16 *xh, *xl, *w31h, *w31l, *w2h, *w2l;
        cudaGetSymbolAddress((void**)&xh,  g_xhi);
        cudaGetSymbolAddress((void**)&xl,  g_xlo);
        cudaGetSymbolAddress((void**)&w31h, g_w31hi);
        cudaGetSymbolAddress((void**)&w31l, g_w31lo);
        cudaGetSymbolAddress((void**)&w2h, g_w2hi);
        cudaGetSymbolAddress((void**)&w2l, g_w2lo);
        int n4x  = (T_TOK * H_DIM) / 4;
        int n4w1 = (int)(((size_t)N_EXP * NG1 * H_DIM) / 4);
        int n4w2 = (int)(((size_t)N_EXP * H_DIM * I_DIM) / 4);
        split_kernel<<<(n4x + 255) / 256, 256>>>(x, xh, xl, n4x);
        split_kernel<<<(n4w1 + 255) / 256, 256>>>(w3w1, w31h, w31l, n4w1);
        split_kernel<<<(n4w2 + 255) / 256, 256>>>(w2, w2h, w2l, n4w2);
    }

    dim3 blk(256);
    dim3 g1(NG1 / BN, T_TOK / BM, N_EXP);    // 44 x 32 x 8
    moe_gemm_kernel<0><<<g1, blk, SMEM_DYN>>>();

    dim3 ga((I_DIM / 4 + 255) / 256, MAXP);
    act_kernel<<<ga, 256>>>();

    dim3 g2(H_DIM / BN, T_TOK / BM, N_EXP);  // 8 x 32 x 8
    moe_gemm_kernel<1><<<g2, blk, SMEM_DYN>>>();

    combine_kernel<<<(T_TOK * (H_DIM / 4) + 255) / 256, 256>>>(out);
}